// round 15
// baseline (speedup 1.0000x reference)
#include <cuda_runtime.h>
#include <cuda_bf16.h>
#include <math.h>

// B=16, N=300, U=100, V=200, E=128, H=8, hd=16, L=3
// out: [16, 20000, 128] f32 (163.8 MB)

// Scratch (allocation-free: device globals)
__device__ float g_hE[16 * 38400];
__device__ float g_pu[16 * 100 * 128];
__device__ float g_pv[16 * 200 * 128];

// ---------------------------------------------------------------------------
// adj dtype detection, inlined per consumer CTA. 2048-word window:
//   any word == 0x3F800000           -> float32
//   any word not in {0,1,0x3F800000} -> packed uint8 (p=0.3 -> certain)
//   else                             -> int32
// ---------------------------------------------------------------------------
template <int NT>
__device__ __forceinline__ int detect_adj_mode(const void* adjraw, int* s_flags)
{
    const unsigned int* aw = (const unsigned int*)adjraw;
    int tid = threadIdx.x;
    if (tid == 0) { s_flags[0] = 0; s_flags[1] = 0; }
    __syncthreads();
    int f32 = 0, multi = 0;
    #pragma unroll
    for (int i = tid; i < 2048; i += NT) {
        unsigned int v = aw[i];
        f32   |= (v == 0x3F800000u);
        multi |= (v != 0u && v != 1u && v != 0x3F800000u);
    }
    if (__any_sync(0xffffffffu, f32)   && (tid & 31) == 0) atomicOr(&s_flags[0], 1);
    if (__any_sync(0xffffffffu, multi) && (tid & 31) == 0) atomicOr(&s_flags[1], 1);
    __syncthreads();
    return s_flags[0] ? 2 : (s_flags[1] ? 1 : 0);   // 2=f32, 1=u8, 0=i32
}

// ---------------------------------------------------------------------------
// Fused 3-layer GAT: one CTA per (b, head). 768 threads (24 warps).
// NEW: shared score matrix E[100][204] built ONCE per layer (unshifted
// exp — |e| <~ 40 so no overflow; masked entries exactly 0). Both the U
// (row) and V (column) aggregations read E directly; denominators folded
// into the aggregation loop. Halves exp count, deletes staging stores
// and the duplicate mask/lrelu pass.
// smem floats:
//   [0,4800)      sWh   [300][16]
//   [4800,9600)   shh   persistent h [300][16]
//   [9600,9856)   sWt   16x16 transposed
//   [9856,9872)   sa1   [9872,9888) sa2
//   [9888,10188)  se1[300]   [10188,10488) se2[300]
//   [10488,15488) sadj (20000 B, canonical u8)
//   [15488,35888) sE    [100][204] (padded rows -> conflict-free)
// total 143552 bytes -> 1 CTA/SM, 24 warps
// ---------------------------------------------------------------------------
#define GAT_THREADS 768

__global__ void __launch_bounds__(GAT_THREADS, 1) gat_fused_kernel(
    const float* __restrict__ hin,
    const void*  __restrict__ adjraw,
    const float* __restrict__ Wl,   // [3][8][16][16]
    const float* __restrict__ al,   // [3][8][32]
    float* __restrict__ hout)
{
    extern __shared__ float sm[];
    float* sWh = sm;
    float* shh = sm + 4800;
    float* sWt = sm + 9600;
    float* sa1 = sm + 9856;
    float* sa2 = sm + 9872;
    float* se1 = sm + 9888;
    float* se2 = sm + 10188;
    unsigned char* sadj = (unsigned char*)(sm + 10488);
    float* sE = sm + 15488;                 // [100][204]
    __shared__ int s_flags[2];

    const int tid  = threadIdx.x;
    const int lane = tid & 31;
    const int w    = tid >> 5;
    const int b    = blockIdx.x >> 3;
    const int hh   = blockIdx.x & 7;

    const float* hsrc = hin + (b * 8 + hh) * 4800;
    float* hdst = hout + (b * 8 + hh) * 4800;

    const int mode = detect_adj_mode<GAT_THREADS>(adjraw, s_flags);

    // ---- one-time loads ----
    for (int i = tid; i < 1200; i += GAT_THREADS)
        ((float4*)shh)[i] = ((const float4*)hsrc)[i];

    if (mode == 1) {
        const uint4* src = (const uint4*)((const unsigned char*)adjraw + b * 20000);
        for (int i = tid; i < 1250; i += GAT_THREADS)
            ((uint4*)sadj)[i] = src[i];
    } else if (mode == 0) {
        const int4* src = (const int4*)((const int*)adjraw + b * 20000);
        for (int i = tid; i < 5000; i += GAT_THREADS) {
            int4 v = src[i];
            ((uchar4*)sadj)[i] = make_uchar4(v.x != 0, v.y != 0, v.z != 0, v.w != 0);
        }
    } else {
        const float4* src = (const float4*)((const float*)adjraw + b * 20000);
        for (int i = tid; i < 5000; i += GAT_THREADS) {
            float4 v = src[i];
            ((uchar4*)sadj)[i] = make_uchar4(v.x != 0.f, v.y != 0.f, v.z != 0.f, v.w != 0.f);
        }
    }

    for (int l = 0; l < 3; l++) {
        const float* W = Wl + (l * 8 + hh) * 256;
        const float* a = al + (l * 8 + hh) * 32;
        if (tid < 256) {
            int j = tid >> 4, k = tid & 15;
            sWt[k * 16 + j] = W[tid];      // sWt[k][j] = W[j][k]
        }
        if (tid < 16) { sa1[tid] = a[tid]; sa2[tid] = a[16 + tid]; }
        __syncthreads();

        // ---- Wh = h @ W^T, e1 = Wh.a1, e2 = Wh.a2 ----
        for (int base = tid; base < 4800; base += GAT_THREADS) {
            int n = base >> 4, jj = base & 15;
            const float* hr = shh + n * 16;
            float s = 0.f;
            #pragma unroll
            for (int k = 0; k < 16; k++) s = fmaf(hr[k], sWt[k * 16 + jj], s);
            sWh[base] = s;
            float p1 = s * sa1[jj];
            float p2 = s * sa2[jj];
            #pragma unroll
            for (int off = 8; off; off >>= 1) {
                p1 += __shfl_xor_sync(0xffffffffu, p1, off);
                p2 += __shfl_xor_sync(0xffffffffu, p2, off);
            }
            if (jj == 0) { se1[n] = p1; se2[n] = p2; }
        }
        __syncthreads();

        // ---- build E[u][v] = adj ? 0 : exp(lrelu(se1[u] + se2[100+v])) ----
        // 5000 quads; thread handles 4 consecutive v's of one u row.
        for (int i = tid; i < 5000; i += GAT_THREADS) {
            int u = i / 50, q = (i - u * 50) << 2;
            uchar4 a4 = *(const uchar4*)(sadj + u * 200 + q);
            float4 c  = *(const float4*)(se2 + 100 + q);
            float r1 = se1[u];
            float4 E;
            float t;
            t = r1 + c.x; t = (t > 0.f) ? t : 0.01f * t; E.x = a4.x ? 0.f : __expf(t);
            t = r1 + c.y; t = (t > 0.f) ? t : 0.01f * t; E.y = a4.y ? 0.f : __expf(t);
            t = r1 + c.z; t = (t > 0.f) ? t : 0.01f * t; E.z = a4.z ? 0.f : __expf(t);
            t = r1 + c.w; t = (t > 0.f) ? t : 0.01f * t; E.w = a4.w ? 0.f : __expf(t);
            *(float4*)&sE[u * 204 + q] = E;
        }
        __syncthreads();

        // ---- aggregation: 75 groups of 4 rows, r8 LPT schedule ----
        for (int k = 0; k < 4; k++) {
            int g;
            if (k == 0)      g = w;                                   // U0..U23
            else if (k == 1) g = (w == 3) ? 24
                               : (25 + w - (w > 3 ? 1 : 0));          // U24 / V25..47
            else if (k == 2) g = 48 + w;                              // V48..71
            else { if (w >= 3) break; g = 72 + w; }                   // V72..74

            const bool modeU = (g < 25);
            const int  r0    = modeU ? (g << 2) : ((g - 25) << 2);

            const int q4 = (lane & 3) << 2, v4 = lane >> 2;
            float4 acc[4];
            float ssum[4] = {0.f, 0.f, 0.f, 0.f};
            #pragma unroll
            for (int r = 0; r < 4; r++) acc[r] = make_float4(0.f, 0.f, 0.f, 0.f);

            if (modeU) {
                // rows u0..u0+3; iterate i over 200 v's
                const float* whb = sWh + 100 * 16 + q4;
                const float* Er  = sE + r0 * 204;
                #pragma unroll 5
                for (int ii = 0; ii < 25; ii++) {
                    int i = v4 + (ii << 3);
                    float4 w4 = *(const float4*)&whb[i * 16];
                    float a0 = Er[i];
                    float a1 = Er[204 + i];
                    float a2 = Er[408 + i];
                    float a3 = Er[612 + i];
                    ssum[0] += a0; ssum[1] += a1; ssum[2] += a2; ssum[3] += a3;
                    acc[0].x = fmaf(a0, w4.x, acc[0].x);
                    acc[0].y = fmaf(a0, w4.y, acc[0].y);
                    acc[0].z = fmaf(a0, w4.z, acc[0].z);
                    acc[0].w = fmaf(a0, w4.w, acc[0].w);
                    acc[1].x = fmaf(a1, w4.x, acc[1].x);
                    acc[1].y = fmaf(a1, w4.y, acc[1].y);
                    acc[1].z = fmaf(a1, w4.z, acc[1].z);
                    acc[1].w = fmaf(a1, w4.w, acc[1].w);
                    acc[2].x = fmaf(a2, w4.x, acc[2].x);
                    acc[2].y = fmaf(a2, w4.y, acc[2].y);
                    acc[2].z = fmaf(a2, w4.z, acc[2].z);
                    acc[2].w = fmaf(a2, w4.w, acc[2].w);
                    acc[3].x = fmaf(a3, w4.x, acc[3].x);
                    acc[3].y = fmaf(a3, w4.y, acc[3].y);
                    acc[3].z = fmaf(a3, w4.z, acc[3].z);
                    acc[3].w = fmaf(a3, w4.w, acc[3].w);
                }
            } else {
                // rows v0..v0+3 (nodes 100+); iterate i over 100 u's
                const float* whb = sWh + q4;
                const float* Ec  = sE + r0;
                #pragma unroll 4
                for (int ii = 0; ii < 13; ii++) {
                    int i = v4 + (ii << 3);
                    if (i < 100) {
                        float4 w4 = *(const float4*)&whb[i * 16];
                        float4 a4 = *(const float4*)&Ec[i * 204];
                        ssum[0] += a4.x; ssum[1] += a4.y;
                        ssum[2] += a4.z; ssum[3] += a4.w;
                        acc[0].x = fmaf(a4.x, w4.x, acc[0].x);
                        acc[0].y = fmaf(a4.x, w4.y, acc[0].y);
                        acc[0].z = fmaf(a4.x, w4.z, acc[0].z);
                        acc[0].w = fmaf(a4.x, w4.w, acc[0].w);
                        acc[1].x = fmaf(a4.y, w4.x, acc[1].x);
                        acc[1].y = fmaf(a4.y, w4.y, acc[1].y);
                        acc[1].z = fmaf(a4.y, w4.z, acc[1].z);
                        acc[1].w = fmaf(a4.y, w4.w, acc[1].w);
                        acc[2].x = fmaf(a4.z, w4.x, acc[2].x);
                        acc[2].y = fmaf(a4.z, w4.y, acc[2].y);
                        acc[2].z = fmaf(a4.z, w4.z, acc[2].z);
                        acc[2].w = fmaf(a4.z, w4.w, acc[2].w);
                        acc[3].x = fmaf(a4.w, w4.x, acc[3].x);
                        acc[3].y = fmaf(a4.w, w4.y, acc[3].y);
                        acc[3].z = fmaf(a4.w, w4.z, acc[3].z);
                        acc[3].w = fmaf(a4.w, w4.w, acc[3].w);
                    }
                }
            }
            // tree-reduce acc + ssum across v4 (offsets 4, 8, 16)
            #pragma unroll
            for (int off = 4; off < 32; off <<= 1) {
                #pragma unroll
                for (int r = 0; r < 4; r++) {
                    acc[r].x += __shfl_xor_sync(0xffffffffu, acc[r].x, off);
                    acc[r].y += __shfl_xor_sync(0xffffffffu, acc[r].y, off);
                    acc[r].z += __shfl_xor_sync(0xffffffffu, acc[r].z, off);
                    acc[r].w += __shfl_xor_sync(0xffffffffu, acc[r].w, off);
                    ssum[r]  += __shfl_xor_sync(0xffffffffu, ssum[r], off);
                }
            }
            if (v4 == 0) {
                #pragma unroll
                for (int r = 0; r < 4; r++) {
                    int node = modeU ? (r0 + r) : (100 + r0 + r);
                    float se = se1[node] + se2[node];
                    se = (se > 0.f) ? se : 0.01f * se;
                    float es  = __expf(se);
                    float inv = 1.f / (ssum[r] + es);
                    float4 ws = *(const float4*)&sWh[node * 16 + q4];
                    float4 res;
                    res.x = (acc[r].x + es * ws.x) * inv;
                    res.y = (acc[r].y + es * ws.y) * inv;
                    res.z = (acc[r].z + es * ws.z) * inv;
                    res.w = (acc[r].w + es * ws.w) * inv;
                    res.x = (res.x > 0.f) ? res.x : expm1f(res.x);
                    res.y = (res.y > 0.f) ? res.y : expm1f(res.y);
                    res.z = (res.z > 0.f) ? res.z : expm1f(res.z);
                    res.w = (res.w > 0.f) ? res.w : expm1f(res.w);
                    if (l == 2)
                        *(float4*)&hdst[node * 16 + q4] = res;
                    else
                        *(float4*)&shh[node * 16 + q4] = res;
                }
            }
        }
        __syncthreads();   // shh fully written before next layer's Wh phase
    }
}

// ---------------------------------------------------------------------------
// pu = hE[:, :U] @ W1^T ; pv = hE[:, U:] @ W2^T   (r8 exact)
// ---------------------------------------------------------------------------
__global__ void __launch_bounds__(256, 1) pupv_kernel(
    const float* __restrict__ hE,
    const float* __restrict__ Wlast,  // [128][257]
    float* __restrict__ pu, float* __restrict__ pv)
{
    extern __shared__ float sm[];
    float* hsm = sm;           // 20*132
    float* Wsm = sm + 2640;    // 128*132

    const int blk = blockIdx.x;
    const int b = blk / 15, t = blk % 15;
    const bool isU = (t < 5);
    const int n0 = isU ? t * 20 : 100 + (t - 5) * 20;
    const int coff = isU ? 0 : 128;
    const int tid = threadIdx.x;

    for (int i = tid; i < 128 * 128; i += 256) {
        int e = i >> 7, k = i & 127;
        Wsm[e * 132 + k] = Wlast[e * 257 + coff + k];
    }
    for (int i = tid; i < 20 * 128; i += 256) {
        int n = i >> 7, k = i & 127;
        hsm[n * 132 + k] = hE[b * 38400 + (n0 + n) * 128 + k];
    }
    __syncthreads();

    const int e = tid & 127, half = tid >> 7;
    float acc[10];
    #pragma unroll
    for (int n = 0; n < 10; n++) acc[n] = 0.f;
    const float* wrow  = Wsm + e * 132;
    const float* hbase = hsm + (half * 10) * 132;

    #pragma unroll 8
    for (int k4 = 0; k4 < 32; k4++) {
        float4 wv = *(const float4*)&wrow[k4 * 4];
        #pragma unroll
        for (int n = 0; n < 10; n++) {
            float4 hv = *(const float4*)&hbase[n * 132 + k4 * 4];
            acc[n] = fmaf(wv.x, hv.x, acc[n]);
            acc[n] = fmaf(wv.y, hv.y, acc[n]);
            acc[n] = fmaf(wv.z, hv.z, acc[n]);
            acc[n] = fmaf(wv.w, hv.w, acc[n]);
        }
    }
    int nodeBase = isU ? (b * 100 + n0 + half * 10) : (b * 200 + (n0 - 100) + half * 10);
    float* dst = isU ? (pu + (size_t)nodeBase * 128) : (pv + (size_t)nodeBase * 128);
    #pragma unroll
    for (int n = 0; n < 10; n++) dst[n * 128 + e] = acc[n];
}

// ---------------------------------------------------------------------------
// out[b,u,v,:] = mask*(pu[b,u,:] + pv[b,v,:]) + weights[b,u,v]*wl
// r14 tiled version: grid 16b x 4u x 4v = 256 CTAs, 256 thr, smem 39KB.
// ---------------------------------------------------------------------------
__global__ void __launch_bounds__(256, 2) out_kernel(
    const float* __restrict__ pu, const float* __restrict__ pv,
    const void* __restrict__ adjraw, const float* __restrict__ weights,
    const float* __restrict__ Wlast, float* __restrict__ out)
{
    extern __shared__ float sm[];
    float* spu = sm;            // 25*128 = 3200
    float* spv = sm + 3200;     // 50*128 = 6400
    float* swl = sm + 9600;     // 128
    __shared__ int s_flags[2];

    const int blk = blockIdx.x;
    const int b  = blk >> 4;
    const int us = (blk >> 2) & 3;
    const int vs = blk & 3;
    const int u0 = us * 25;
    const int v0 = vs * 50;
    const int tid = threadIdx.x, lane = tid & 31, w = tid >> 5;

    const int mode = detect_adj_mode<256>(adjraw, s_flags);

    for (int i = tid; i < 800; i += 256)    // pu tile: 25*32 float4
        ((float4*)spu)[i] = ((const float4*)(pu + (b * 100 + u0) * 128))[i];
    for (int i = tid; i < 1600; i += 256)   // pv tile: 50*32 float4
        ((float4*)spv)[i] = ((const float4*)(pv + (b * 200 + v0) * 128))[i];
    if (tid < 128) swl[tid] = Wlast[tid * 257 + 256];
    __syncthreads();

    const float4 wl4 = *(const float4*)&swl[lane * 4];
    for (int iu = 0; iu < 25; iu++) {
        const int u = u0 + iu;
        const int abase = (b * 100 + u) * 200;
        const float* wrow = weights + abase;
        const float4 pu4 = *(const float4*)&spu[iu * 128 + lane * 4];
        float* obase = out + (((size_t)(b * 100 + u)) * 200 + v0) * 128;
        for (int iv = w; iv < 50; iv += 8) {
            const int v = v0 + iv;
            float msk;
            if (mode == 0)      msk = ((const int*)adjraw)[abase + v] ? 0.f : 1.f;
            else if (mode == 1) msk = ((const unsigned char*)adjraw)[abase + v] ? 0.f : 1.f;
            else                msk = (((const float*)adjraw)[abase + v] != 0.f) ? 0.f : 1.f;
            const float wt  = wrow[v];
            const float4 pv4 = *(const float4*)&spv[iv * 128 + lane * 4];
            float4 o;
            o.x = msk * (pu4.x + pv4.x) + wt * wl4.x;
            o.y = msk * (pu4.y + pv4.y) + wt * wl4.y;
            o.z = msk * (pu4.z + pv4.z) + wt * wl4.z;
            o.w = msk * (pu4.w + pv4.w) + wt * wl4.w;
            __stcs((float4*)&obase[(size_t)iv * 128 + lane * 4], o);
        }
    }
}

// ---------------------------------------------------------------------------
extern "C" void kernel_launch(void* const* d_in, const int* in_sizes, int n_in,
                              void* d_out, int out_size)
{
    (void)in_sizes; (void)n_in; (void)out_size;
    const float* x              = (const float*)d_in[0];
    const void*  adj_raw        = (const void*)d_in[1];
    const float* weights        = (const float*)d_in[2];
    const float* Wlayers        = (const float*)d_in[3];
    const float* alayers        = (const float*)d_in[4];
    const float* Wlast          = (const float*)d_in[5];
    float* out = (float*)d_out;

    float *dH, *dpu, *dpv;
    cudaGetSymbolAddress((void**)&dH, g_hE);
    cudaGetSymbolAddress((void**)&dpu, g_pu);
    cudaGetSymbolAddress((void**)&dpv, g_pv);

    const int SM1 = 35888 * 4;                  // 143552
    const int SM2 = (2640 + 128 * 132) * 4;     // 78144
    const int SM3 = (9600 + 128) * 4 + 256;     // ~39KB
    cudaFuncSetAttribute(gat_fused_kernel, cudaFuncAttributeMaxDynamicSharedMemorySize, SM1);
    cudaFuncSetAttribute(pupv_kernel,      cudaFuncAttributeMaxDynamicSharedMemorySize, SM2);
    cudaFuncSetAttribute(out_kernel,       cudaFuncAttributeMaxDynamicSharedMemorySize, SM3);

    gat_fused_kernel<<<128, GAT_THREADS, SM1>>>(x, adj_raw, Wlayers, alayers, dH);
    pupv_kernel<<<240, 256, SM2>>>(dH, Wlast, dpu, dpv);
    out_kernel<<<256, 256, SM3>>>(dpu, dpv, adj_raw, weights, Wlast, out);
}

// round 16
// speedup vs baseline: 1.0536x; 1.0536x over previous
#include <cuda_runtime.h>
#include <cuda_bf16.h>
#include <math.h>

// B=16, N=300, U=100, V=200, E=128, H=8, hd=16, L=3
// out: [16, 20000, 128] f32 (163.8 MB)

// Scratch (allocation-free: device globals)
__device__ float g_hE[16 * 38400];
__device__ float g_pu[16 * 100 * 128];
__device__ float g_pv[16 * 200 * 128];

// Grid barrier state (generation-based, safe across graph replays)
__device__ volatile unsigned int g_count;
__device__ volatile unsigned int g_gen;

#define NBLOCKS 128
#define GAT_THREADS 768

__device__ __forceinline__ void grid_barrier()
{
    __syncthreads();
    if (threadIdx.x == 0) {
        __threadfence();
        unsigned int gen = g_gen;
        if (atomicAdd((unsigned int*)&g_count, 1u) == NBLOCKS - 1) {
            g_count = 0;
            __threadfence();
            g_gen = gen + 1;
        } else {
            while (g_gen == gen) { }
        }
        __threadfence();
    }
    __syncthreads();
}

// ---------------------------------------------------------------------------
// adj dtype detection (2048-word window):
//   any word == 0x3F800000           -> float32
//   any word not in {0,1,0x3F800000} -> packed uint8 (p=0.3 -> certain)
//   else                             -> int32
// ---------------------------------------------------------------------------
__device__ __forceinline__ int detect_adj_mode(const void* adjraw, int* s_flags)
{
    const unsigned int* aw = (const unsigned int*)adjraw;
    int tid = threadIdx.x;
    if (tid == 0) { s_flags[0] = 0; s_flags[1] = 0; }
    __syncthreads();
    int f32 = 0, multi = 0;
    #pragma unroll
    for (int i = tid; i < 2048; i += GAT_THREADS) {
        unsigned int v = aw[i];
        f32   |= (v == 0x3F800000u);
        multi |= (v != 0u && v != 1u && v != 0x3F800000u);
    }
    if (__any_sync(0xffffffffu, f32)   && (tid & 31) == 0) atomicOr(&s_flags[0], 1);
    if (__any_sync(0xffffffffu, multi) && (tid & 31) == 0) atomicOr(&s_flags[1], 1);
    __syncthreads();
    return s_flags[0] ? 2 : (s_flags[1] ? 1 : 0);   // 2=f32, 1=u8, 0=i32
}

// ---------------------------------------------------------------------------
// ONE persistent kernel, 128 CTAs (one per (b,head)), 768 threads, 3 phases:
//  P1: fused 3-layer GAT (r14 internals, tied-best 75.4us config)
//  P2: pu/pv projections, grid-strided over 240 tiles
//  P3: output assembly, (b, u-slice) mapping, streaming stores
// smem floats (phase 1 layout; P2 uses [0,19536), P3 uses [0,27392)):
//   [0,4800)      sWh   [300][16]
//   [4800,9600)   shh   persistent h [300][16]
//   [9600,9856)   sWt   16x16 transposed
//   [9856,9872)   sa1   [9872,9888) sa2
//   [9888,10188)  se1[300]   [10188,10488) se2[300]
//   [10488,15488) sadj (20000 B, canonical u8)
//   [15488,35072) sattb [24 warps][204][4]
// total 140288 bytes -> 1 CTA/SM, all 128 CTAs wave-1 resident
// ---------------------------------------------------------------------------
__global__ void __launch_bounds__(GAT_THREADS, 1) fused_all_kernel(
    const float* __restrict__ hin,
    const void*  __restrict__ adjraw,
    const float* __restrict__ Wl,     // [3][8][16][16]
    const float* __restrict__ al,     // [3][8][32]
    const float* __restrict__ Wlast,  // [128][257]
    const float* __restrict__ weights,
    float* __restrict__ hE,
    float* __restrict__ pu, float* __restrict__ pv,
    float* __restrict__ out)
{
    extern __shared__ float sm[];
    float* sWh = sm;
    float* shh = sm + 4800;
    float* sWt = sm + 9600;
    float* sa1 = sm + 9856;
    float* sa2 = sm + 9872;
    float* se1 = sm + 9888;
    float* se2 = sm + 10188;
    unsigned char* sadj = (unsigned char*)(sm + 10488);
    float* sattb = sm + 15488;
    __shared__ int s_flags[2];

    const int tid  = threadIdx.x;
    const int lane = tid & 31;
    const int w    = tid >> 5;
    const int b    = blockIdx.x >> 3;
    const int hh   = blockIdx.x & 7;

    const float* hsrc = hin + (b * 8 + hh) * 4800;
    float* hdst = hE + (b * 8 + hh) * 4800;

    const int mode = detect_adj_mode(adjraw, s_flags);

    // ======================= PHASE 1: fused GAT =======================
    for (int i = tid; i < 1200; i += GAT_THREADS)
        ((float4*)shh)[i] = ((const float4*)hsrc)[i];

    if (mode == 1) {
        const uint4* src = (const uint4*)((const unsigned char*)adjraw + b * 20000);
        for (int i = tid; i < 1250; i += GAT_THREADS)
            ((uint4*)sadj)[i] = src[i];
    } else if (mode == 0) {
        const int4* src = (const int4*)((const int*)adjraw + b * 20000);
        for (int i = tid; i < 5000; i += GAT_THREADS) {
            int4 v = src[i];
            ((uchar4*)sadj)[i] = make_uchar4(v.x != 0, v.y != 0, v.z != 0, v.w != 0);
        }
    } else {
        const float4* src = (const float4*)((const float*)adjraw + b * 20000);
        for (int i = tid; i < 5000; i += GAT_THREADS) {
            float4 v = src[i];
            ((uchar4*)sadj)[i] = make_uchar4(v.x != 0.f, v.y != 0.f, v.z != 0.f, v.w != 0.f);
        }
    }

    for (int l = 0; l < 3; l++) {
        const float* W = Wl + (l * 8 + hh) * 256;
        const float* a = al + (l * 8 + hh) * 32;
        if (tid < 256) {
            int j = tid >> 4, k = tid & 15;
            sWt[k * 16 + j] = W[tid];      // sWt[k][j] = W[j][k]
        }
        if (tid < 16) { sa1[tid] = a[tid]; sa2[tid] = a[16 + tid]; }
        __syncthreads();

        // Wh = h @ W^T, e1 = Wh.a1, e2 = Wh.a2
        for (int base = tid; base < 4800; base += GAT_THREADS) {
            int n = base >> 4, jj = base & 15;
            const float* hr = shh + n * 16;
            float s = 0.f;
            #pragma unroll
            for (int k = 0; k < 16; k++) s = fmaf(hr[k], sWt[k * 16 + jj], s);
            sWh[base] = s;
            float p1 = s * sa1[jj];
            float p2 = s * sa2[jj];
            #pragma unroll
            for (int off = 8; off; off >>= 1) {
                p1 += __shfl_xor_sync(0xffffffffu, p1, off);
                p2 += __shfl_xor_sync(0xffffffffu, p2, off);
            }
            if (jj == 0) { se1[n] = p1; se2[n] = p2; }
        }
        __syncthreads();

        // attention: 75 groups of 4 rows, LPT schedule
        for (int k = 0; k < 4; k++) {
            int g;
            if (k == 0)      g = w;                                   // U0..U23
            else if (k == 1) g = (w == 3) ? 24
                               : (25 + w - (w > 3 ? 1 : 0));          // U24 / V25..47
            else if (k == 2) g = 48 + w;                              // V48..71
            else { if (w >= 3) break; g = 72 + w; }                   // V72..74

            const bool modeU = (g < 25);
            const int  r0    = modeU ? (g << 2) : ((g - 25) << 2);

            float* ab = sattb + w * 816;       // [204][4] per warp
            float rowc[4], selfe[4];
            float ssum[4] = {0.f, 0.f, 0.f, 0.f};

            if (modeU) {
                #pragma unroll
                for (int r = 0; r < 4; r++) {
                    rowc[r]  = se1[r0 + r];
                    float t  = rowc[r] + se2[r0 + r];
                    selfe[r] = (t > 0.f) ? t : 0.01f * t;
                }
                const float* cb = se2 + 100;
                const unsigned char* adjU = sadj + r0 * 200;
                #pragma unroll
                for (int kk = 0; kk < 6; kk++) {
                    int idx = lane + (kk << 5);
                    float cv = cb[idx];
                    float4 st;
                    float ev;
                    #define SCORE_U(r, comp) { \
                        float t = rowc[r] + cv; \
                        t = (t > 0.f) ? t : 0.01f * t; \
                        ev = __expf(t - selfe[r]); \
                        ev = adjU[r * 200 + idx] ? 0.f : ev; \
                        st.comp = ev; ssum[r] += ev; }
                    SCORE_U(0, x) SCORE_U(1, y) SCORE_U(2, z) SCORE_U(3, w)
                    *(float4*)&ab[idx * 4] = st;
                }
                if (lane < 8) {
                    int idx = 192 + lane;
                    float cv = cb[idx];
                    float4 st;
                    float ev;
                    SCORE_U(0, x) SCORE_U(1, y) SCORE_U(2, z) SCORE_U(3, w)
                    *(float4*)&ab[idx * 4] = st;
                    #undef SCORE_U
                }
            } else {
                #pragma unroll
                for (int r = 0; r < 4; r++) {
                    int node = 100 + r0 + r;
                    rowc[r]  = se2[node];
                    float t  = se1[node] + rowc[r];
                    selfe[r] = (t > 0.f) ? t : 0.01f * t;
                }
                const unsigned char* adjC = sadj + r0;
                #pragma unroll
                for (int kk = 0; kk < 3; kk++) {
                    int idx = lane + (kk << 5);
                    float cv = se1[idx];
                    unsigned int aw4 = *(const unsigned int*)(adjC + idx * 200);
                    float4 st;
                    float ev;
                    #define SCORE_V(r, comp) { \
                        float t = rowc[r] + cv; \
                        t = (t > 0.f) ? t : 0.01f * t; \
                        ev = __expf(t - selfe[r]); \
                        ev = ((aw4 >> (r * 8)) & 255u) ? 0.f : ev; \
                        st.comp = ev; ssum[r] += ev; }
                    SCORE_V(0, x) SCORE_V(1, y) SCORE_V(2, z) SCORE_V(3, w)
                    *(float4*)&ab[idx * 4] = st;
                }
                if (lane < 4) {
                    int idx = 96 + lane;
                    float cv = se1[idx];
                    unsigned int aw4 = *(const unsigned int*)(adjC + idx * 200);
                    float4 st;
                    float ev;
                    SCORE_V(0, x) SCORE_V(1, y) SCORE_V(2, z) SCORE_V(3, w)
                    *(float4*)&ab[idx * 4] = st;
                    #undef SCORE_V
                }
            }
            __syncwarp();

            #pragma unroll
            for (int off = 16; off; off >>= 1) {
                #pragma unroll
                for (int r = 0; r < 4; r++)
                    ssum[r] += __shfl_xor_sync(0xffffffffu, ssum[r], off);
            }
            float inv[4];
            #pragma unroll
            for (int r = 0; r < 4; r++)
                inv[r] = 1.f / (ssum[r] + 1.f);

            const int q4 = (lane & 3) << 2, v4 = lane >> 2;
            float4 acc[4];
            #pragma unroll
            for (int r = 0; r < 4; r++) acc[r] = make_float4(0.f, 0.f, 0.f, 0.f);

            if (modeU) {
                const float* whb = sWh + 100 * 16 + q4;
                #pragma unroll 5
                for (int ii = 0; ii < 25; ii++) {
                    int i = v4 + (ii << 3);
                    float4 w4 = *(const float4*)&whb[i * 16];
                    float4 a4 = *(const float4*)&ab[i * 4];
                    acc[0].x = fmaf(a4.x, w4.x, acc[0].x);
                    acc[0].y = fmaf(a4.x, w4.y, acc[0].y);
                    acc[0].z = fmaf(a4.x, w4.z, acc[0].z);
                    acc[0].w = fmaf(a4.x, w4.w, acc[0].w);
                    acc[1].x = fmaf(a4.y, w4.x, acc[1].x);
                    acc[1].y = fmaf(a4.y, w4.y, acc[1].y);
                    acc[1].z = fmaf(a4.y, w4.z, acc[1].z);
                    acc[1].w = fmaf(a4.y, w4.w, acc[1].w);
                    acc[2].x = fmaf(a4.z, w4.x, acc[2].x);
                    acc[2].y = fmaf(a4.z, w4.y, acc[2].y);
                    acc[2].z = fmaf(a4.z, w4.z, acc[2].z);
                    acc[2].w = fmaf(a4.z, w4.w, acc[2].w);
                    acc[3].x = fmaf(a4.w, w4.x, acc[3].x);
                    acc[3].y = fmaf(a4.w, w4.y, acc[3].y);
                    acc[3].z = fmaf(a4.w, w4.z, acc[3].z);
                    acc[3].w = fmaf(a4.w, w4.w, acc[3].w);
                }
            } else {
                const float* whb = sWh + q4;
                #pragma unroll 4
                for (int ii = 0; ii < 13; ii++) {
                    int i = v4 + (ii << 3);
                    if (i < 100) {
                        float4 w4 = *(const float4*)&whb[i * 16];
                        float4 a4 = *(const float4*)&ab[i * 4];
                        acc[0].x = fmaf(a4.x, w4.x, acc[0].x);
                        acc[0].y = fmaf(a4.x, w4.y, acc[0].y);
                        acc[0].z = fmaf(a4.x, w4.z, acc[0].z);
                        acc[0].w = fmaf(a4.x, w4.w, acc[0].w);
                        acc[1].x = fmaf(a4.y, w4.x, acc[1].x);
                        acc[1].y = fmaf(a4.y, w4.y, acc[1].y);
                        acc[1].z = fmaf(a4.y, w4.z, acc[1].z);
                        acc[1].w = fmaf(a4.y, w4.w, acc[1].w);
                        acc[2].x = fmaf(a4.z, w4.x, acc[2].x);
                        acc[2].y = fmaf(a4.z, w4.y, acc[2].y);
                        acc[2].z = fmaf(a4.z, w4.z, acc[2].z);
                        acc[2].w = fmaf(a4.z, w4.w, acc[2].w);
                        acc[3].x = fmaf(a4.w, w4.x, acc[3].x);
                        acc[3].y = fmaf(a4.w, w4.y, acc[3].y);
                        acc[3].z = fmaf(a4.w, w4.z, acc[3].z);
                        acc[3].w = fmaf(a4.w, w4.w, acc[3].w);
                    }
                }
            }
            #pragma unroll
            for (int off = 4; off < 32; off <<= 1) {
                #pragma unroll
                for (int r = 0; r < 4; r++) {
                    acc[r].x += __shfl_xor_sync(0xffffffffu, acc[r].x, off);
                    acc[r].y += __shfl_xor_sync(0xffffffffu, acc[r].y, off);
                    acc[r].z += __shfl_xor_sync(0xffffffffu, acc[r].z, off);
                    acc[r].w += __shfl_xor_sync(0xffffffffu, acc[r].w, off);
                }
            }
            if (v4 == 0) {
                #pragma unroll
                for (int r = 0; r < 4; r++) {
                    int node = modeU ? (r0 + r) : (100 + r0 + r);
                    float4 ws = *(const float4*)&sWh[node * 16 + q4];
                    float4 res;
                    res.x = (acc[r].x + ws.x) * inv[r];
                    res.y = (acc[r].y + ws.y) * inv[r];
                    res.z = (acc[r].z + ws.z) * inv[r];
                    res.w = (acc[r].w + ws.w) * inv[r];
                    res.x = (res.x > 0.f) ? res.x : expm1f(res.x);
                    res.y = (res.y > 0.f) ? res.y : expm1f(res.y);
                    res.z = (res.z > 0.f) ? res.z : expm1f(res.z);
                    res.w = (res.w > 0.f) ? res.w : expm1f(res.w);
                    if (l == 2)
                        *(float4*)&hdst[node * 16 + q4] = res;
                    else
                        *(float4*)&shh[node * 16 + q4] = res;
                }
            }
            __syncwarp();
        }
        __syncthreads();
    }

    grid_barrier();   // hE complete

    // ======================= PHASE 2: pu/pv =======================
    {
        float* hsm = sm;           // 20*132 = 2640
        float* Wsm = sm + 2640;    // 128*132 = 16896
        for (int t = blockIdx.x; t < 240; t += NBLOCKS) {
            int b2 = t / 15, tt = t - b2 * 15;
            bool isU = (tt < 5);
            int n0 = isU ? tt * 20 : 100 + (tt - 5) * 20;
            int coff = isU ? 0 : 128;
            for (int i = tid; i < 16384; i += GAT_THREADS) {
                int e = i >> 7, k = i & 127;
                Wsm[e * 132 + k] = Wlast[e * 257 + coff + k];
            }
            for (int i = tid; i < 2560; i += GAT_THREADS) {
                int n = i >> 7, k = i & 127;
                hsm[n * 132 + k] = hE[b2 * 38400 + (n0 + n) * 128 + k];
            }
            __syncthreads();

            int e = tid & 127, grp = tid >> 7;   // grp 0..5; 5 idle
            if (grp < 5) {
                float acc[4] = {0.f, 0.f, 0.f, 0.f};
                const float* wrow  = Wsm + e * 132;
                const float* hbase = hsm + (grp * 4) * 132;
                #pragma unroll 8
                for (int k4 = 0; k4 < 32; k4++) {
                    float4 wv = *(const float4*)&wrow[k4 * 4];
                    #pragma unroll
                    for (int n = 0; n < 4; n++) {
                        float4 hv = *(const float4*)&hbase[n * 132 + k4 * 4];
                        acc[n] = fmaf(wv.x, hv.x, acc[n]);
                        acc[n] = fmaf(wv.y, hv.y, acc[n]);
                        acc[n] = fmaf(wv.z, hv.z, acc[n]);
                        acc[n] = fmaf(wv.w, hv.w, acc[n]);
                    }
                }
                int nodeBase = isU ? (b2 * 100 + n0 + grp * 4)
                                   : (b2 * 200 + (n0 - 100) + grp * 4);
                float* dst = (isU ? pu : pv) + (size_t)nodeBase * 128;
                #pragma unroll
                for (int n = 0; n < 4; n++) dst[n * 128 + e] = acc[n];
            }
            __syncthreads();
        }
    }

    grid_barrier();   // pu/pv complete

    // ======================= PHASE 3: output =======================
    {
        float* spv = sm;            // 200*128 = 25600
        float* spu = sm + 25600;    // up to 13*128
        float* swl = sm + 27264;    // 128

        const int b3 = blockIdx.x >> 3, sl = blockIdx.x & 7;
        const int u0 = (sl * 100) >> 3;
        const int u1 = ((sl + 1) * 100) >> 3;
        const int nu = u1 - u0;

        for (int i = tid; i < 6400; i += GAT_THREADS)
            ((float4*)spv)[i] = ((const float4*)(pv + (size_t)b3 * 25600))[i];
        for (int i = tid; i < nu * 32; i += GAT_THREADS)
            ((float4*)spu)[i] = ((const float4*)(pu + (size_t)(b3 * 100 + u0) * 128))[i];
        if (tid < 128) swl[tid] = Wlast[tid * 257 + 256];
        __syncthreads();

        const float4 wl4 = *(const float4*)&swl[lane * 4];
        for (int iu = 0; iu < nu; iu++) {
            const int u = u0 + iu;
            const int abase = (b3 * 100 + u) * 200;
            const float* wrow = weights + abase;
            const float4 pu4 = *(const float4*)&spu[iu * 128 + lane * 4];
            float* obase = out + ((size_t)(b3 * 100 + u)) * 200 * 128;
            for (int v = w; v < 200; v += 24) {
                float msk;
                if (mode == 0)      msk = ((const int*)adjraw)[abase + v] ? 0.f : 1.f;
                else if (mode == 1) msk = ((const unsigned char*)adjraw)[abase + v] ? 0.f : 1.f;
                else                msk = (((const float*)adjraw)[abase + v] != 0.f) ? 0.f : 1.f;
                const float wt  = wrow[v];
                const float4 pv4 = *(const float4*)&spv[v * 128 + lane * 4];
                float4 o;
                o.x = msk * (pu4.x + pv4.x) + wt * wl4.x;
                o.y = msk * (pu4.y + pv4.y) + wt * wl4.y;
                o.z = msk * (pu4.z + pv4.z) + wt * wl4.z;
                o.w = msk * (pu4.w + pv4.w) + wt * wl4.w;
                __stcs((float4*)&obase[(size_t)v * 128 + lane * 4], o);
            }
        }
    }
}

// ---------------------------------------------------------------------------
extern "C" void kernel_launch(void* const* d_in, const int* in_sizes, int n_in,
                              void* d_out, int out_size)
{
    (void)in_sizes; (void)n_in; (void)out_size;
    const float* x              = (const float*)d_in[0];
    const void*  adj_raw        = (const void*)d_in[1];
    const float* weights        = (const float*)d_in[2];
    const float* Wlayers        = (const float*)d_in[3];
    const float* alayers        = (const float*)d_in[4];
    const float* Wlast          = (const float*)d_in[5];
    float* out = (float*)d_out;

    float *dH, *dpu, *dpv;
    cudaGetSymbolAddress((void**)&dH, g_hE);
    cudaGetSymbolAddress((void**)&dpu, g_pu);
    cudaGetSymbolAddress((void**)&dpv, g_pv);

    const int SM1 = 35072 * 4;                  // 140288
    cudaFuncSetAttribute(fused_all_kernel, cudaFuncAttributeMaxDynamicSharedMemorySize, SM1);

    fused_all_kernel<<<NBLOCKS, GAT_THREADS, SM1>>>(
        x, adj_raw, Wlayers, alayers, Wlast, weights, dH, dpu, dpv, out);
}

// round 17
// speedup vs baseline: 1.1292x; 1.0718x over previous
#include <cuda_runtime.h>
#include <cuda_bf16.h>
#include <math.h>

// B=16, N=300, U=100, V=200, E=128, H=8, hd=16, L=3
// out: [16, 20000, 128] f32 (163.8 MB)

// Scratch (allocation-free: device globals)
__device__ float g_hE[16 * 38400];
__device__ float g_pu[16 * 100 * 128];
__device__ float g_pv[16 * 200 * 128];

// Grid barrier state (generation-based, safe across graph replays)
__device__ volatile unsigned int g_count;
__device__ volatile unsigned int g_gen;

#define NBLOCKS 128
#define GAT_THREADS 768

__device__ __forceinline__ void grid_barrier()
{
    __syncthreads();
    if (threadIdx.x == 0) {
        __threadfence();
        unsigned int gen = g_gen;
        if (atomicAdd((unsigned int*)&g_count, 1u) == NBLOCKS - 1) {
            g_count = 0;
            __threadfence();
            g_gen = gen + 1;
        } else {
            while (g_gen == gen) { }
        }
        __threadfence();
    }
    __syncthreads();
}

// ---------------------------------------------------------------------------
// adj dtype detection (2048-word window):
//   any word == 0x3F800000           -> float32
//   any word not in {0,1,0x3F800000} -> packed uint8 (p=0.3 -> certain)
//   else                             -> int32
// ---------------------------------------------------------------------------
__device__ __forceinline__ int detect_adj_mode(const void* adjraw, int* s_flags)
{
    const unsigned int* aw = (const unsigned int*)adjraw;
    int tid = threadIdx.x;
    if (tid == 0) { s_flags[0] = 0; s_flags[1] = 0; }
    __syncthreads();
    int f32 = 0, multi = 0;
    #pragma unroll
    for (int i = tid; i < 2048; i += GAT_THREADS) {
        unsigned int v = aw[i];
        f32   |= (v == 0x3F800000u);
        multi |= (v != 0u && v != 1u && v != 0x3F800000u);
    }
    if (__any_sync(0xffffffffu, f32)   && (tid & 31) == 0) atomicOr(&s_flags[0], 1);
    if (__any_sync(0xffffffffu, multi) && (tid & 31) == 0) atomicOr(&s_flags[1], 1);
    __syncthreads();
    return s_flags[0] ? 2 : (s_flags[1] ? 1 : 0);   // 2=f32, 1=u8, 0=i32
}

// ---------------------------------------------------------------------------
// ONE persistent kernel, 128 CTAs (one per (b,head)), 768 threads, 3 phases:
//  P1: fused 3-layer GAT  + EARLY WRITE of masked outputs (weights*wl only,
//      independent of GAT -> rides phase 1's idle DRAM)
//  P2: pu/pv projections, grid-strided over 240 tiles
//  P3: output assembly, unmasked entries only, streaming stores
// smem floats (phase 1 layout):
//   [0,4800)      sWh   [300][16]
//   [4800,9600)   shh   persistent h [300][16]
//   [9600,9856)   sWt   16x16 transposed
//   [9856,9872)   sa1   [9872,9888) sa2
//   [9888,10188)  se1[300]   [10188,10488) se2[300]
//   [10488,15488) sadj (20000 B, canonical u8)
//   [15488,35072) sattb [24 warps][204][4]
//   [35072,35200) swl
// total 140800 bytes -> 1 CTA/SM, all 128 CTAs wave-1 resident
// ---------------------------------------------------------------------------
__global__ void __launch_bounds__(GAT_THREADS, 1) fused_all_kernel(
    const float* __restrict__ hin,
    const void*  __restrict__ adjraw,
    const float* __restrict__ Wl,     // [3][8][16][16]
    const float* __restrict__ al,     // [3][8][32]
    const float* __restrict__ Wlast,  // [128][257]
    const float* __restrict__ weights,
    float* __restrict__ hE,
    float* __restrict__ pu, float* __restrict__ pv,
    float* __restrict__ out)
{
    extern __shared__ float sm[];
    float* sWh = sm;
    float* shh = sm + 4800;
    float* sWt = sm + 9600;
    float* sa1 = sm + 9856;
    float* sa2 = sm + 9872;
    float* se1 = sm + 9888;
    float* se2 = sm + 10188;
    unsigned char* sadj = (unsigned char*)(sm + 10488);
    float* sattb = sm + 15488;
    float* swl   = sm + 35072;
    __shared__ int s_flags[2];

    const int tid  = threadIdx.x;
    const int lane = tid & 31;
    const int w    = tid >> 5;
    const int b    = blockIdx.x >> 3;
    const int hh   = blockIdx.x & 7;

    const float* hsrc = hin + (b * 8 + hh) * 4800;
    float* hdst = hE + (b * 8 + hh) * 4800;

    const int mode = detect_adj_mode(adjraw, s_flags);

    // ======================= PHASE 1: fused GAT =======================
    for (int i = tid; i < 1200; i += GAT_THREADS)
        ((float4*)shh)[i] = ((const float4*)hsrc)[i];

    if (mode == 1) {
        const uint4* src = (const uint4*)((const unsigned char*)adjraw + b * 20000);
        for (int i = tid; i < 1250; i += GAT_THREADS)
            ((uint4*)sadj)[i] = src[i];
    } else if (mode == 0) {
        const int4* src = (const int4*)((const int*)adjraw + b * 20000);
        for (int i = tid; i < 5000; i += GAT_THREADS) {
            int4 v = src[i];
            ((uchar4*)sadj)[i] = make_uchar4(v.x != 0, v.y != 0, v.z != 0, v.w != 0);
        }
    } else {
        const float4* src = (const float4*)((const float*)adjraw + b * 20000);
        for (int i = tid; i < 5000; i += GAT_THREADS) {
            float4 v = src[i];
            ((uchar4*)sadj)[i] = make_uchar4(v.x != 0.f, v.y != 0.f, v.z != 0.f, v.w != 0.f);
        }
    }
    if (tid < 128) swl[tid] = Wlast[tid * 257 + 256];
    __syncthreads();

    // ---- EARLY WRITE: masked outputs = weights * wl (GAT-independent).
    //      Same (b, u-slice) mapping as phase 3 -> each (b,u,v) written once.
    {
        const int u0 = (hh * 100) >> 3;
        const int u1 = ((hh + 1) * 100) >> 3;
        const int total = (u1 - u0) * 200;
        const float4 wl4 = *(const float4*)&swl[lane * 4];
        for (int p = w; p < total; p += 24) {
            int iu = p / 200, v = p - iu * 200;
            int u = u0 + iu;
            if (sadj[u * 200 + v]) {
                float wt = weights[(b * 100 + u) * 200 + v];
                float4 o;
                o.x = wt * wl4.x; o.y = wt * wl4.y;
                o.z = wt * wl4.z; o.w = wt * wl4.w;
                __stcs((float4*)&out[(((size_t)(b * 100 + u)) * 200 + v) * 128 + lane * 4], o);
            }
        }
    }

    for (int l = 0; l < 3; l++) {
        const float* W = Wl + (l * 8 + hh) * 256;
        const float* a = al + (l * 8 + hh) * 32;
        if (tid < 256) {
            int j = tid >> 4, k = tid & 15;
            sWt[k * 16 + j] = W[tid];      // sWt[k][j] = W[j][k]
        }
        if (tid < 16) { sa1[tid] = a[tid]; sa2[tid] = a[16 + tid]; }
        __syncthreads();

        // Wh = h @ W^T, e1 = Wh.a1, e2 = Wh.a2
        for (int base = tid; base < 4800; base += GAT_THREADS) {
            int n = base >> 4, jj = base & 15;
            const float* hr = shh + n * 16;
            float s = 0.f;
            #pragma unroll
            for (int k = 0; k < 16; k++) s = fmaf(hr[k], sWt[k * 16 + jj], s);
            sWh[base] = s;
            float p1 = s * sa1[jj];
            float p2 = s * sa2[jj];
            #pragma unroll
            for (int off = 8; off; off >>= 1) {
                p1 += __shfl_xor_sync(0xffffffffu, p1, off);
                p2 += __shfl_xor_sync(0xffffffffu, p2, off);
            }
            if (jj == 0) { se1[n] = p1; se2[n] = p2; }
        }
        __syncthreads();

        // attention: 75 groups of 4 rows, LPT schedule
        for (int k = 0; k < 4; k++) {
            int g;
            if (k == 0)      g = w;                                   // U0..U23
            else if (k == 1) g = (w == 3) ? 24
                               : (25 + w - (w > 3 ? 1 : 0));          // U24 / V25..47
            else if (k == 2) g = 48 + w;                              // V48..71
            else { if (w >= 3) break; g = 72 + w; }                   // V72..74

            const bool modeU = (g < 25);
            const int  r0    = modeU ? (g << 2) : ((g - 25) << 2);

            float* ab = sattb + w * 816;       // [204][4] per warp
            float rowc[4], selfe[4];
            float ssum[4] = {0.f, 0.f, 0.f, 0.f};

            if (modeU) {
                #pragma unroll
                for (int r = 0; r < 4; r++) {
                    rowc[r]  = se1[r0 + r];
                    float t  = rowc[r] + se2[r0 + r];
                    selfe[r] = (t > 0.f) ? t : 0.01f * t;
                }
                const float* cb = se2 + 100;
                const unsigned char* adjU = sadj + r0 * 200;
                #pragma unroll
                for (int kk = 0; kk < 6; kk++) {
                    int idx = lane + (kk << 5);
                    float cv = cb[idx];
                    float4 st;
                    float ev;
                    #define SCORE_U(r, comp) { \
                        float t = rowc[r] + cv; \
                        t = (t > 0.f) ? t : 0.01f * t; \
                        ev = __expf(t - selfe[r]); \
                        ev = adjU[r * 200 + idx] ? 0.f : ev; \
                        st.comp = ev; ssum[r] += ev; }
                    SCORE_U(0, x) SCORE_U(1, y) SCORE_U(2, z) SCORE_U(3, w)
                    *(float4*)&ab[idx * 4] = st;
                }
                if (lane < 8) {
                    int idx = 192 + lane;
                    float cv = cb[idx];
                    float4 st;
                    float ev;
                    SCORE_U(0, x) SCORE_U(1, y) SCORE_U(2, z) SCORE_U(3, w)
                    *(float4*)&ab[idx * 4] = st;
                    #undef SCORE_U
                }
            } else {
                #pragma unroll
                for (int r = 0; r < 4; r++) {
                    int node = 100 + r0 + r;
                    rowc[r]  = se2[node];
                    float t  = se1[node] + rowc[r];
                    selfe[r] = (t > 0.f) ? t : 0.01f * t;
                }
                const unsigned char* adjC = sadj + r0;
                #pragma unroll
                for (int kk = 0; kk < 3; kk++) {
                    int idx = lane + (kk << 5);
                    float cv = se1[idx];
                    unsigned int aw4 = *(const unsigned int*)(adjC + idx * 200);
                    float4 st;
                    float ev;
                    #define SCORE_V(r, comp) { \
                        float t = rowc[r] + cv; \
                        t = (t > 0.f) ? t : 0.01f * t; \
                        ev = __expf(t - selfe[r]); \
                        ev = ((aw4 >> (r * 8)) & 255u) ? 0.f : ev; \
                        st.comp = ev; ssum[r] += ev; }
                    SCORE_V(0, x) SCORE_V(1, y) SCORE_V(2, z) SCORE_V(3, w)
                    *(float4*)&ab[idx * 4] = st;
                }
                if (lane < 4) {
                    int idx = 96 + lane;
                    float cv = se1[idx];
                    unsigned int aw4 = *(const unsigned int*)(adjC + idx * 200);
                    float4 st;
                    float ev;
                    SCORE_V(0, x) SCORE_V(1, y) SCORE_V(2, z) SCORE_V(3, w)
                    *(float4*)&ab[idx * 4] = st;
                    #undef SCORE_V
                }
            }
            __syncwarp();

            #pragma unroll
            for (int off = 16; off; off >>= 1) {
                #pragma unroll
                for (int r = 0; r < 4; r++)
                    ssum[r] += __shfl_xor_sync(0xffffffffu, ssum[r], off);
            }
            float inv[4];
            #pragma unroll
            for (int r = 0; r < 4; r++)
                inv[r] = 1.f / (ssum[r] + 1.f);

            const int q4 = (lane & 3) << 2, v4 = lane >> 2;
            float4 acc[4];
            #pragma unroll
            for (int r = 0; r < 4; r++) acc[r] = make_float4(0.f, 0.f, 0.f, 0.f);

            if (modeU) {
                const float* whb = sWh + 100 * 16 + q4;
                #pragma unroll 5
                for (int ii = 0; ii < 25; ii++) {
                    int i = v4 + (ii << 3);
                    float4 w4 = *(const float4*)&whb[i * 16];
                    float4 a4 = *(const float4*)&ab[i * 4];
                    acc[0].x = fmaf(a4.x, w4.x, acc[0].x);
                    acc[0].y = fmaf(a4.x, w4.y, acc[0].y);
                    acc[0].z = fmaf(a4.x, w4.z, acc[0].z);
                    acc[0].w = fmaf(a4.x, w4.w, acc[0].w);
                    acc[1].x = fmaf(a4.y, w4.x, acc[1].x);
                    acc[1].y = fmaf(a4.y, w4.y, acc[1].y);
                    acc[1].z = fmaf(a4.y, w4.z, acc[1].z);
                    acc[1].w = fmaf(a4.y, w4.w, acc[1].w);
                    acc[2].x = fmaf(a4.z, w4.x, acc[2].x);
                    acc[2].y = fmaf(a4.z, w4.y, acc[2].y);
                    acc[2].z = fmaf(a4.z, w4.z, acc[2].z);
                    acc[2].w = fmaf(a4.z, w4.w, acc[2].w);
                    acc[3].x = fmaf(a4.w, w4.x, acc[3].x);
                    acc[3].y = fmaf(a4.w, w4.y, acc[3].y);
                    acc[3].z = fmaf(a4.w, w4.z, acc[3].z);
                    acc[3].w = fmaf(a4.w, w4.w, acc[3].w);
                }
            } else {
                const float* whb = sWh + q4;
                #pragma unroll 4
                for (int ii = 0; ii < 13; ii++) {
                    int i = v4 + (ii << 3);
                    if (i < 100) {
                        float4 w4 = *(const float4*)&whb[i * 16];
                        float4 a4 = *(const float4*)&ab[i * 4];
                        acc[0].x = fmaf(a4.x, w4.x, acc[0].x);
                        acc[0].y = fmaf(a4.x, w4.y, acc[0].y);
                        acc[0].z = fmaf(a4.x, w4.z, acc[0].z);
                        acc[0].w = fmaf(a4.x, w4.w, acc[0].w);
                        acc[1].x = fmaf(a4.y, w4.x, acc[1].x);
                        acc[1].y = fmaf(a4.y, w4.y, acc[1].y);
                        acc[1].z = fmaf(a4.y, w4.z, acc[1].z);
                        acc[1].w = fmaf(a4.y, w4.w, acc[1].w);
                        acc[2].x = fmaf(a4.z, w4.x, acc[2].x);
                        acc[2].y = fmaf(a4.z, w4.y, acc[2].y);
                        acc[2].z = fmaf(a4.z, w4.z, acc[2].z);
                        acc[2].w = fmaf(a4.z, w4.w, acc[2].w);
                        acc[3].x = fmaf(a4.w, w4.x, acc[3].x);
                        acc[3].y = fmaf(a4.w, w4.y, acc[3].y);
                        acc[3].z = fmaf(a4.w, w4.z, acc[3].z);
                        acc[3].w = fmaf(a4.w, w4.w, acc[3].w);
                    }
                }
            }
            #pragma unroll
            for (int off = 4; off < 32; off <<= 1) {
                #pragma unroll
                for (int r = 0; r < 4; r++) {
                    acc[r].x += __shfl_xor_sync(0xffffffffu, acc[r].x, off);
                    acc[r].y += __shfl_xor_sync(0xffffffffu, acc[r].y, off);
                    acc[r].z += __shfl_xor_sync(0xffffffffu, acc[r].z, off);
                    acc[r].w += __shfl_xor_sync(0xffffffffu, acc[r].w, off);
                }
            }
            if (v4 == 0) {
                #pragma unroll
                for (int r = 0; r < 4; r++) {
                    int node = modeU ? (r0 + r) : (100 + r0 + r);
                    float4 ws = *(const float4*)&sWh[node * 16 + q4];
                    float4 res;
                    res.x = (acc[r].x + ws.x) * inv[r];
                    res.y = (acc[r].y + ws.y) * inv[r];
                    res.z = (acc[r].z + ws.z) * inv[r];
                    res.w = (acc[r].w + ws.w) * inv[r];
                    res.x = (res.x > 0.f) ? res.x : expm1f(res.x);
                    res.y = (res.y > 0.f) ? res.y : expm1f(res.y);
                    res.z = (res.z > 0.f) ? res.z : expm1f(res.z);
                    res.w = (res.w > 0.f) ? res.w : expm1f(res.w);
                    if (l == 2)
                        *(float4*)&hdst[node * 16 + q4] = res;
                    else
                        *(float4*)&shh[node * 16 + q4] = res;
                }
            }
            __syncwarp();
        }
        __syncthreads();
    }

    grid_barrier();   // hE complete

    // ======================= PHASE 2: pu/pv =======================
    {
        float* hsm = sm;           // 20*132 = 2640
        float* Wsm = sm + 2640;    // 128*132 = 16896
        for (int t = blockIdx.x; t < 240; t += NBLOCKS) {
            int b2 = t / 15, tt = t - b2 * 15;
            bool isU = (tt < 5);
            int n0 = isU ? tt * 20 : 100 + (tt - 5) * 20;
            int coff = isU ? 0 : 128;
            for (int i = tid; i < 16384; i += GAT_THREADS) {
                int e = i >> 7, k = i & 127;
                Wsm[e * 132 + k] = Wlast[e * 257 + coff + k];
            }
            for (int i = tid; i < 2560; i += GAT_THREADS) {
                int n = i >> 7, k = i & 127;
                hsm[n * 132 + k] = hE[b2 * 38400 + (n0 + n) * 128 + k];
            }
            __syncthreads();

            int e = tid & 127, grp = tid >> 7;   // grp 0..5; 5 idle
            if (grp < 5) {
                float acc[4] = {0.f, 0.f, 0.f, 0.f};
                const float* wrow  = Wsm + e * 132;
                const float* hbase = hsm + (grp * 4) * 132;
                #pragma unroll 8
                for (int k4 = 0; k4 < 32; k4++) {
                    float4 wv = *(const float4*)&wrow[k4 * 4];
                    #pragma unroll
                    for (int n = 0; n < 4; n++) {
                        float4 hv = *(const float4*)&hbase[n * 132 + k4 * 4];
                        acc[n] = fmaf(wv.x, hv.x, acc[n]);
                        acc[n] = fmaf(wv.y, hv.y, acc[n]);
                        acc[n] = fmaf(wv.z, hv.z, acc[n]);
                        acc[n] = fmaf(wv.w, hv.w, acc[n]);
                    }
                }
                int nodeBase = isU ? (b2 * 100 + n0 + grp * 4)
                                   : (b2 * 200 + (n0 - 100) + grp * 4);
                float* dst = (isU ? pu : pv) + (size_t)nodeBase * 128;
                #pragma unroll
                for (int n = 0; n < 4; n++) dst[n * 128 + e] = acc[n];
            }
            __syncthreads();
        }
    }

    grid_barrier();   // pu/pv complete

    // ======================= PHASE 3: output (unmasked only) ============
    {
        float* spv = sm;            // 200*128 = 25600
        float* spu = sm + 25600;    // up to 13*128
        float* swl3 = sm + 27264;   // 128

        const int b3 = blockIdx.x >> 3, sl = blockIdx.x & 7;
        const int u0 = (sl * 100) >> 3;
        const int u1 = ((sl + 1) * 100) >> 3;
        const int nu = u1 - u0;

        for (int i = tid; i < 6400; i += GAT_THREADS)
            ((float4*)spv)[i] = ((const float4*)(pv + (size_t)b3 * 25600))[i];
        for (int i = tid; i < nu * 32; i += GAT_THREADS)
            ((float4*)spu)[i] = ((const float4*)(pu + (size_t)(b3 * 100 + u0) * 128))[i];
        if (tid < 128) swl3[tid] = Wlast[tid * 257 + 256];
        __syncthreads();

        const float4 wl4 = *(const float4*)&swl3[lane * 4];
        for (int iu = 0; iu < nu; iu++) {
            const int u = u0 + iu;
            const int abase = (b3 * 100 + u) * 200;
            const float* wrow = weights + abase;
            const float4 pu4 = *(const float4*)&spu[iu * 128 + lane * 4];
            float* obase = out + ((size_t)(b3 * 100 + u)) * 200 * 128;
            for (int v = w; v < 200; v += 24) {
                bool masked;
                if (mode == 0)      masked = ((const int*)adjraw)[abase + v] != 0;
                else if (mode == 1) masked = ((const unsigned char*)adjraw)[abase + v] != 0;
                else                masked = ((const float*)adjraw)[abase + v] != 0.f;
                if (masked) continue;          // written in phase 1
                const float wt  = wrow[v];
                const float4 pv4 = *(const float4*)&spv[v * 128 + lane * 4];
                float4 o;
                o.x = (pu4.x + pv4.x) + wt * wl4.x;
                o.y = (pu4.y + pv4.y) + wt * wl4.y;
                o.z = (pu4.z + pv4.z) + wt * wl4.z;
                o.w = (pu4.w + pv4.w) + wt * wl4.w;
                __stcs((float4*)&obase[(size_t)v * 128 + lane * 4], o);
            }
        }
    }
}

// ---------------------------------------------------------------------------
extern "C" void kernel_launch(void* const* d_in, const int* in_sizes, int n_in,
                              void* d_out, int out_size)
{
    (void)in_sizes; (void)n_in; (void)out_size;
    const float* x              = (const float*)d_in[0];
    const void*  adj_raw        = (const void*)d_in[1];
    const float* weights        = (const float*)d_in[2];
    const float* Wlayers        = (const float*)d_in[3];
    const float* alayers        = (const float*)d_in[4];
    const float* Wlast          = (const float*)d_in[5];
    float* out = (float*)d_out;

    float *dH, *dpu, *dpv;
    cudaGetSymbolAddress((void**)&dH, g_hE);
    cudaGetSymbolAddress((void**)&dpu, g_pu);
    cudaGetSymbolAddress((void**)&dpv, g_pv);

    const int SM1 = 35200 * 4;                  // 140800
    cudaFuncSetAttribute(fused_all_kernel, cudaFuncAttributeMaxDynamicSharedMemorySize, SM1);

    fused_all_kernel<<<NBLOCKS, GAT_THREADS, SM1>>>(
        x, adj_raw, Wlayers, alayers, Wlast, weights, dH, dpu, dpv, out);
}